// round 1
// baseline (speedup 1.0000x reference)
#include <cuda_runtime.h>
#include <cstdint>

// GCN 2-layer: out = spmm(relu(spmm(X)@W1))@W2
// N=50000 nodes, E=850000 edges, D=64 throughout.
// Strategy:
//   zero(agg); scatter(X -> agg); gemm(agg,W1 -> h, relu);
//   zero(agg); scatter(h -> agg); gemm(agg,W2 -> d_out)
// Scatter uses red.global.add.v4.f32 (1 vector atomic per 16B).
// Edge index dtype (int64 vs int32) detected at runtime.

#define D 64
#define NMAX 50176

__device__ float g_agg[NMAX * D];
__device__ float g_h[NMAX * D];
__device__ int g_is64;

// ---------------------------------------------------------------------------
// Detect whether the edge index buffer is int64 or int32.
// If int64 (little-endian), every high 32-bit word of the first 64 entries is 0
// (node ids < 50000). If int32, those words are random node ids; the chance
// that all 64 are zero is (1/50000)^64 ~ 0.
// ---------------------------------------------------------------------------
__global__ void detect_kernel(const int* __restrict__ w) {
    if (threadIdx.x == 0) {
        int is64 = 1;
        #pragma unroll 1
        for (int i = 0; i < 64; i++) {
            if (w[2 * i + 1] != 0) { is64 = 0; break; }
        }
        g_is64 = is64;
    }
}

// ---------------------------------------------------------------------------
// Zero-fill (vectorized)
// ---------------------------------------------------------------------------
__global__ void zero_kernel(float4* __restrict__ p, int n4) {
    int i = blockIdx.x * blockDim.x + threadIdx.x;
    if (i < n4) p[i] = make_float4(0.f, 0.f, 0.f, 0.f);
}

// ---------------------------------------------------------------------------
// Scatter SPMM: out[dst] += deg[src]*deg[dst] * feat[src]
// 16 threads per edge, one float4 (16B) per thread, one vector RED per thread.
// ---------------------------------------------------------------------------
__global__ void __launch_bounds__(256) scatter_kernel(
    const float4* __restrict__ feat,   // [N, 16] float4 view of [N, 64]
    const void*   __restrict__ ei,     // [2, E] int64 or int32
    const float*  __restrict__ dis,    // [N]
    float*        __restrict__ out,    // [N, 64], pre-zeroed
    int E)
{
    int idx = blockIdx.x * 256 + threadIdx.x;
    int e = idx >> 4;
    if (e >= E) return;
    int lane = idx & 15;

    long long s, d;
    if (g_is64) {
        const long long* p = (const long long*)ei;
        s = p[e];
        d = p[E + e];
    } else {
        const int* p = (const int*)ei;
        s = p[e];
        d = p[E + e];
    }

    float c = dis[s] * dis[d];
    float4 v = feat[(int)s * 16 + lane];
    float* o = out + (int)d * 64 + lane * 4;

    asm volatile("red.global.add.v4.f32 [%0], {%1, %2, %3, %4};"
                 :: "l"(o), "f"(c * v.x), "f"(c * v.y), "f"(c * v.z), "f"(c * v.w)
                 : "memory");
}

// ---------------------------------------------------------------------------
// Dense GEMM: Y[n,64] = X[n,64] @ W[64,64], optional relu on output.
// Block: 256 threads handle 256 rows. Thread: 4 rows x 16 cols register tile.
// W staged in smem (16 KB); X read via float4 loads (L1-resident per block).
// ---------------------------------------------------------------------------
__global__ void __launch_bounds__(256) gemm64_kernel(
    const float* __restrict__ X,
    const float* __restrict__ W,
    float*       __restrict__ Y,
    int n, int relu)
{
    __shared__ float Ws[64 * 64];
    #pragma unroll
    for (int i = threadIdx.x; i < 1024; i += 256)
        ((float4*)Ws)[i] = ((const float4*)W)[i];
    __syncthreads();

    int rg = threadIdx.x >> 2;          // 0..63
    int cg = (threadIdx.x & 3) << 4;    // 0,16,32,48
    int r0 = blockIdx.x * 256 + (rg << 2);

    float acc[4][16];
    #pragma unroll
    for (int i = 0; i < 4; i++)
        #pragma unroll
        for (int j = 0; j < 16; j++)
            acc[i][j] = 0.f;

    const float4* X4 = (const float4*)X;

    #pragma unroll 4
    for (int k4 = 0; k4 < 16; k4++) {
        float4 xv[4];
        #pragma unroll
        for (int i = 0; i < 4; i++) {
            int r = r0 + i;
            xv[i] = (r < n) ? X4[r * 16 + k4] : make_float4(0.f, 0.f, 0.f, 0.f);
        }
        #pragma unroll
        for (int kk = 0; kk < 4; kk++) {
            const float* wrow = &Ws[(k4 * 4 + kk) * 64 + cg];
            float4 w0 = *(const float4*)(wrow + 0);
            float4 w1 = *(const float4*)(wrow + 4);
            float4 w2 = *(const float4*)(wrow + 8);
            float4 w3 = *(const float4*)(wrow + 12);
            #pragma unroll
            for (int i = 0; i < 4; i++) {
                float xs = (kk == 0) ? xv[i].x : (kk == 1) ? xv[i].y
                         : (kk == 2) ? xv[i].z : xv[i].w;
                acc[i][0]  += xs * w0.x; acc[i][1]  += xs * w0.y;
                acc[i][2]  += xs * w0.z; acc[i][3]  += xs * w0.w;
                acc[i][4]  += xs * w1.x; acc[i][5]  += xs * w1.y;
                acc[i][6]  += xs * w1.z; acc[i][7]  += xs * w1.w;
                acc[i][8]  += xs * w2.x; acc[i][9]  += xs * w2.y;
                acc[i][10] += xs * w2.z; acc[i][11] += xs * w2.w;
                acc[i][12] += xs * w3.x; acc[i][13] += xs * w3.y;
                acc[i][14] += xs * w3.z; acc[i][15] += xs * w3.w;
            }
        }
    }

    #pragma unroll
    for (int i = 0; i < 4; i++) {
        int r = r0 + i;
        if (r < n) {
            float* yo = &Y[r * 64 + cg];
            #pragma unroll
            for (int j4 = 0; j4 < 4; j4++) {
                float4 o;
                o.x = acc[i][j4 * 4 + 0];
                o.y = acc[i][j4 * 4 + 1];
                o.z = acc[i][j4 * 4 + 2];
                o.w = acc[i][j4 * 4 + 3];
                if (relu) {
                    o.x = fmaxf(o.x, 0.f); o.y = fmaxf(o.y, 0.f);
                    o.z = fmaxf(o.z, 0.f); o.w = fmaxf(o.w, 0.f);
                }
                *(float4*)(yo + j4 * 4) = o;
            }
        }
    }
}

// ---------------------------------------------------------------------------
// Launch
// ---------------------------------------------------------------------------
extern "C" void kernel_launch(void* const* d_in, const int* in_sizes, int n_in,
                              void* d_out, int out_size)
{
    const float* x   = (const float*)d_in[0];
    const void*  ei  = d_in[1];
    const float* dis = (const float*)d_in[2];
    const float* W1  = (const float*)d_in[n_in - 2];
    const float* W2  = (const float*)d_in[n_in - 1];

    int N = in_sizes[0] / D;
    int E = in_sizes[1] / 2;

    float* agg = nullptr;
    float* h   = nullptr;
    cudaGetSymbolAddress((void**)&agg, g_agg);
    cudaGetSymbolAddress((void**)&h,   g_h);

    int n4    = N * (D / 4);
    int zgrid = (n4 + 255) / 256;
    int sgrid = (E * 16 + 255) / 256;
    int ggrid = (N + 255) / 256;

    detect_kernel<<<1, 32>>>((const int*)ei);

    // Layer 1: agg = spmm(X); h = relu(agg @ W1)
    zero_kernel<<<zgrid, 256>>>((float4*)agg, n4);
    scatter_kernel<<<sgrid, 256>>>((const float4*)x, ei, dis, agg, E);
    gemm64_kernel<<<ggrid, 256>>>(agg, W1, h, N, 1);

    // Layer 2: agg = spmm(h); out = agg @ W2
    zero_kernel<<<zgrid, 256>>>((float4*)agg, n4);
    scatter_kernel<<<sgrid, 256>>>((const float4*)h, ei, dis, agg, E);
    gemm64_kernel<<<ggrid, 256>>>(agg, W2, (float*)d_out, N, 0);
}

// round 2
// speedup vs baseline: 1.1398x; 1.1398x over previous
#include <cuda_runtime.h>
#include <cstdint>

// GCN 2-layer: out = spmm(relu(spmm(X)@W1))@W2,  A_norm = D^-1/2 A D^-1/2
// N=50000, E=850000, D=64.
//
// Factorization used here (dis = deg_inv_sqrt, dis > 0):
//   xs   = dis .* X                          (prescale kernel)
//   agg  = scatter-add xs[src] -> [dst]      (pure gather + RED, no per-edge dis)
//   hs   = relu(dis .* (agg @ W1)) .* dis    (gemm: input-scale via epilogue linearity,
//                                             relu, then src-side scale for layer 2)
//   agg2 = scatter-add hs[src] -> [dst]
//   out  = dis .* (agg2 @ W2)
//
// All feature matrices (12.8MB) are L2-resident; scatter is L2-gather + vector-RED bound.

#define D 64
#define NMAX 50176

__device__ float g_xs[NMAX * D];   // scaled features (layer1: xs, then reused for hs)
__device__ float g_agg[NMAX * D];  // aggregation target
__device__ int g_is64;

// ---------------------------------------------------------------------------
// Edge dtype detection: int64 edge ids < 50000 have zero high words.
// ---------------------------------------------------------------------------
__global__ void detect_kernel(const int* __restrict__ w) {
    if (threadIdx.x == 0) {
        int is64 = 1;
        #pragma unroll 1
        for (int i = 0; i < 64; i++) {
            if (w[2 * i + 1] != 0) { is64 = 0; break; }
        }
        g_is64 = is64;
    }
}

// ---------------------------------------------------------------------------
// Prescale: xs[i,:] = dis[i] * x[i,:]
// ---------------------------------------------------------------------------
__global__ void __launch_bounds__(256) prescale_kernel(
    const float4* __restrict__ x, const float* __restrict__ dis,
    float4* __restrict__ xs, int n4)
{
    int i = blockIdx.x * 256 + threadIdx.x;
    if (i >= n4) return;
    float s = dis[i >> 4];
    float4 v = x[i];
    v.x *= s; v.y *= s; v.z *= s; v.w *= s;
    xs[i] = v;
}

// ---------------------------------------------------------------------------
// Scatter SPMM core: out[dst] += feat[src]   (feat already src-scaled)
// 16 threads/edge, one float4 gather + one red.global.add.v4.f32 each.
// ---------------------------------------------------------------------------
__global__ void __launch_bounds__(256) scatter_kernel(
    const float4* __restrict__ feat,   // [N,16] float4 view
    const void*   __restrict__ ei,     // [2,E] int64 or int32
    float*        __restrict__ out,    // [N,64], pre-zeroed
    int E)
{
    int idx = blockIdx.x * 256 + threadIdx.x;
    int e = idx >> 4;
    if (e >= E) return;
    int lane = idx & 15;

    int s, d;
    if (g_is64) {
        const long long* p = (const long long*)ei;
        s = (int)p[e];
        d = (int)p[E + e];
    } else {
        const int* p = (const int*)ei;
        s = p[e];
        d = p[E + e];
    }

    float4 v = feat[s * 16 + lane];
    float* o = out + d * 64 + lane * 4;

    asm volatile("red.global.add.v4.f32 [%0], {%1, %2, %3, %4};"
                 :: "l"(o), "f"(v.x), "f"(v.y), "f"(v.z), "f"(v.w)
                 : "memory");
}

// ---------------------------------------------------------------------------
// GEMM: Y[r,:] = g(dis[r] * (X[r,:] @ W))  for 64x64 W.
//   mode 0: g(v) = v                      (final output)
//   mode 1: g(v) = relu(v) * dis[r]       (hidden layer, src-scaled for scatter)
// 128 threads/CTA, thread tile = 4 rows x 16 cols, 3 CTAs/SM.
// Input row scale applied in epilogue (linear in row).
// ---------------------------------------------------------------------------
__global__ void __launch_bounds__(128, 3) gemm64_kernel(
    const float* __restrict__ X,
    const float* __restrict__ W,
    const float* __restrict__ dis,
    float*       __restrict__ Y,
    int n, int mode)
{
    __shared__ float Ws[64 * 64];
    #pragma unroll
    for (int i = threadIdx.x; i < 1024; i += 128)
        ((float4*)Ws)[i] = ((const float4*)W)[i];
    __syncthreads();

    int rg = threadIdx.x >> 2;          // 0..31
    int cg = (threadIdx.x & 3) << 4;    // 0,16,32,48
    int r0 = blockIdx.x * 128 + (rg << 2);

    float acc[4][16];
    #pragma unroll
    for (int i = 0; i < 4; i++)
        #pragma unroll
        for (int j = 0; j < 16; j++)
            acc[i][j] = 0.f;

    const float4* X4 = (const float4*)X;

    #pragma unroll 4
    for (int k4 = 0; k4 < 16; k4++) {
        float4 xv[4];
        #pragma unroll
        for (int i = 0; i < 4; i++) {
            int r = r0 + i;
            xv[i] = (r < n) ? X4[r * 16 + k4] : make_float4(0.f, 0.f, 0.f, 0.f);
        }
        #pragma unroll
        for (int kk = 0; kk < 4; kk++) {
            const float* wrow = &Ws[(k4 * 4 + kk) * 64 + cg];
            float4 w0 = *(const float4*)(wrow + 0);
            float4 w1 = *(const float4*)(wrow + 4);
            float4 w2 = *(const float4*)(wrow + 8);
            float4 w3 = *(const float4*)(wrow + 12);
            #pragma unroll
            for (int i = 0; i < 4; i++) {
                float xs = (kk == 0) ? xv[i].x : (kk == 1) ? xv[i].y
                         : (kk == 2) ? xv[i].z : xv[i].w;
                acc[i][0]  += xs * w0.x; acc[i][1]  += xs * w0.y;
                acc[i][2]  += xs * w0.z; acc[i][3]  += xs * w0.w;
                acc[i][4]  += xs * w1.x; acc[i][5]  += xs * w1.y;
                acc[i][6]  += xs * w1.z; acc[i][7]  += xs * w1.w;
                acc[i][8]  += xs * w2.x; acc[i][9]  += xs * w2.y;
                acc[i][10] += xs * w2.z; acc[i][11] += xs * w2.w;
                acc[i][12] += xs * w3.x; acc[i][13] += xs * w3.y;
                acc[i][14] += xs * w3.z; acc[i][15] += xs * w3.w;
            }
        }
    }

    #pragma unroll
    for (int i = 0; i < 4; i++) {
        int r = r0 + i;
        if (r < n) {
            float s = dis[r];
            float* yo = &Y[r * 64 + cg];
            #pragma unroll
            for (int j4 = 0; j4 < 4; j4++) {
                float4 o;
                o.x = acc[i][j4 * 4 + 0] * s;
                o.y = acc[i][j4 * 4 + 1] * s;
                o.z = acc[i][j4 * 4 + 2] * s;
                o.w = acc[i][j4 * 4 + 3] * s;
                if (mode) {
                    o.x = fmaxf(o.x, 0.f) * s; o.y = fmaxf(o.y, 0.f) * s;
                    o.z = fmaxf(o.z, 0.f) * s; o.w = fmaxf(o.w, 0.f) * s;
                }
                *(float4*)(yo + j4 * 4) = o;
            }
        }
    }
}

// ---------------------------------------------------------------------------
// Launch
// ---------------------------------------------------------------------------
extern "C" void kernel_launch(void* const* d_in, const int* in_sizes, int n_in,
                              void* d_out, int out_size)
{
    const float* x   = (const float*)d_in[0];
    const void*  ei  = d_in[1];
    const float* dis = (const float*)d_in[2];
    const float* W1  = (const float*)d_in[n_in - 2];
    const float* W2  = (const float*)d_in[n_in - 1];

    int N = in_sizes[0] / D;
    int E = in_sizes[1] / 2;

    float* xs  = nullptr;
    float* agg = nullptr;
    cudaGetSymbolAddress((void**)&xs,  g_xs);
    cudaGetSymbolAddress((void**)&agg, g_agg);

    size_t bytes = (size_t)N * D * sizeof(float);
    int n4    = N * (D / 4);
    int pgrid = (n4 + 255) / 256;
    int sgrid = (E * 16 + 255) / 256;
    int ggrid = (N + 127) / 128;

    detect_kernel<<<1, 32>>>((const int*)ei);

    // Layer 1
    prescale_kernel<<<pgrid, 256>>>((const float4*)x, dis, (float4*)xs, n4);
    cudaMemsetAsync(agg, 0, bytes);
    scatter_kernel<<<sgrid, 256>>>((const float4*)xs, ei, agg, E);
    gemm64_kernel<<<ggrid, 128>>>(agg, W1, dis, xs, N, 1);   // xs now holds hs

    // Layer 2
    cudaMemsetAsync(agg, 0, bytes);
    scatter_kernel<<<sgrid, 256>>>((const float4*)xs, ei, agg, E);
    gemm64_kernel<<<ggrid, 128>>>(agg, W2, dis, (float*)d_out, N, 0);
}